// round 10
// baseline (speedup 1.0000x reference)
#include <cuda_runtime.h>

#define NG   1024
#define IMGW 192
#define IMGH 192
#define NPIX (IMGW*IMGH)
#define TS   8          // tile size
#define NTX  (IMGW/TS)  // 24 tile cols
#define NSEG 8          // depth segments per pixel
#define NTHR 512        // 64 pixels x 8 segments

// Per-gaussian records:
//  p0 = {gx, gy, radius, opacity_eff (0 if invisible)}
//  p1 = {conA, conB, conC, depth}
//  p2 = {colR, colG, colB, 0}
//  rng = packed tile range c0|c1<<8|r0<<16|r1<<24 (empty if invisible)
//  dk  = depth bits (for sort key)
__device__ float4 g_p0[NG], g_p1[NG], g_p2[NG];
__device__ unsigned g_rng[NG], g_dk[NG];

// 32 blocks x 64 threads. Blocks 0-15: geometry. Blocks 16-31: SH color.
__global__ void __launch_bounds__(64) preprocess_kernel(
                                  const float* __restrict__ means,
                                  const float* __restrict__ scales,
                                  const float* __restrict__ rots,
                                  const float* __restrict__ opac,
                                  const float* __restrict__ shs,
                                  const float* __restrict__ view,
                                  const float* __restrict__ proj,
                                  const float* __restrict__ campos,
                                  float* __restrict__ out)
{
    int bid = blockIdx.x;
    if (bid >= 16) {
        // ---------------- color half ----------------
        int i = (bid - 16) * 64 + threadIdx.x;
        float mx = means[3*i], my = means[3*i+1], mz = means[3*i+2];
        float4 t[12];
        const float4* sh4 = reinterpret_cast<const float4*>(shs + i*48);
        #pragma unroll
        for (int w = 0; w < 12; w++) t[w] = __ldg(sh4 + w);

        float dxc = mx - campos[0], dyc = my - campos[1], dzc = mz - campos[2];
        float inv = rsqrtf(dxc*dxc + dyc*dyc + dzc*dzc);
        float x = dxc*inv, y = dyc*inv, z = dzc*inv;
        float xx = x*x, yy = y*y, zz = z*z, xy = x*y, yz = y*z, xz = x*z;
        float bas[16];
        bas[0]  = 0.28209479177387814f;
        bas[1]  = -0.4886025119029199f * y;
        bas[2]  =  0.4886025119029199f * z;
        bas[3]  = -0.4886025119029199f * x;
        bas[4]  =  1.0925484305920792f * xy;
        bas[5]  = -1.0925484305920792f * yz;
        bas[6]  =  0.31539156525252005f * (2.0f*zz - xx - yy);
        bas[7]  = -1.0925484305920792f * xz;
        bas[8]  =  0.5462742152960396f * (xx - yy);
        bas[9]  = -0.5900435899266435f * y * (3.0f*xx - yy);
        bas[10] =  2.890611442640554f  * xy * z;
        bas[11] = -0.4570457994644658f * y * (4.0f*zz - xx - yy);
        bas[12] =  0.3731763325901154f * z * (2.0f*zz - 3.0f*xx - 3.0f*yy);
        bas[13] = -0.4570457994644658f * x * (4.0f*zz - xx - yy);
        bas[14] =  1.445305721320277f  * z * (xx - yy);
        bas[15] = -0.5900435899266435f * x * (xx - yy - 3.0f*zz);

        float col[3] = {0.5f, 0.5f, 0.5f};
        #pragma unroll
        for (int w = 0; w < 12; w++) {
            float v[4] = {t[w].x, t[w].y, t[w].z, t[w].w};
            #pragma unroll
            for (int j = 0; j < 4; j++) {
                const int flat = 4*w + j;
                col[flat % 3] += bas[flat / 3] * v[j];
            }
        }
        g_p2[i] = make_float4(fmaxf(col[0], 0.0f), fmaxf(col[1], 0.0f),
                              fmaxf(col[2], 0.0f), 0.0f);
        return;
    }

    // ---------------- geometry half ----------------
    int i = bid * 64 + threadIdx.x;
    float mx = means[3*i], my = means[3*i+1], mz = means[3*i+2];

    float4 q = __ldg(reinterpret_cast<const float4*>(rots) + i);
    float qr = q.x, qx = q.y, qy = q.z, qz = q.w;
    float sx = scales[3*i], sy = scales[3*i+1], sz = scales[3*i+2];
    float R00 = 1.0f-2.0f*(qy*qy+qz*qz), R01 = 2.0f*(qx*qy-qr*qz), R02 = 2.0f*(qx*qz+qr*qy);
    float R10 = 2.0f*(qx*qy+qr*qz), R11 = 1.0f-2.0f*(qx*qx+qz*qz), R12 = 2.0f*(qy*qz-qr*qx);
    float R20 = 2.0f*(qx*qz-qr*qy), R21 = 2.0f*(qy*qz+qr*qx), R22 = 1.0f-2.0f*(qx*qx+qy*qy);
    float M00=R00*sx, M01=R01*sy, M02=R02*sz;
    float M10=R10*sx, M11=R11*sy, M12=R12*sz;
    float M20=R20*sx, M21=R21*sy, M22=R22*sz;
    float c00 = M00*M00+M01*M01+M02*M02;
    float c01 = M00*M10+M01*M11+M02*M12;
    float c02 = M00*M20+M01*M21+M02*M22;
    float c11 = M10*M10+M11*M11+M12*M12;
    float c12 = M10*M20+M11*M21+M12*M22;
    float c22 = M20*M20+M21*M21+M22*M22;

    float pvx = view[0]*mx + view[1]*my + view[2]*mz + view[3];
    float pvy = view[4]*mx + view[5]*my + view[6]*mz + view[7];
    float pvz = view[8]*mx + view[9]*my + view[10]*mz + view[11];
    float phx = proj[0]*mx + proj[1]*my + proj[2]*mz + proj[3];
    float phy = proj[4]*mx + proj[5]*my + proj[6]*mz + proj[7];
    float phw = proj[12]*mx + proj[13]*my + proj[14]*mz + proj[15];
    float invw = 1.0f / (phw + 1e-7f);
    float gx = ((phx*invw + 1.0f) * (float)IMGW - 1.0f) * 0.5f;
    float gy = ((phy*invw + 1.0f) * (float)IMGH - 1.0f) * 0.5f;
    float depth = pvz;
    bool in_front = depth > 0.2f;
    float tz = in_front ? depth : 1.0f;
    const float lim = 1.3f * 0.5f;
    float txv = fminf(fmaxf(pvx/tz, -lim), lim) * tz;
    float tyv = fminf(fmaxf(pvy/tz, -lim), lim) * tz;
    const float fx = (float)IMGW / (2.0f*0.5f);
    const float fy = (float)IMGH / (2.0f*0.5f);
    float J00 = fx/tz, J02 = -fx*txv/(tz*tz);
    float J11 = fy/tz, J12 = -fy*tyv/(tz*tz);
    float T00 = J00*view[0] + J02*view[8];
    float T01 = J00*view[1] + J02*view[9];
    float T02 = J00*view[2] + J02*view[10];
    float T10 = J11*view[4] + J12*view[8];
    float T11 = J11*view[5] + J12*view[9];
    float T12 = J11*view[6] + J12*view[10];
    float u0 = c00*T00 + c01*T01 + c02*T02;
    float u1 = c01*T00 + c11*T01 + c12*T02;
    float u2 = c02*T00 + c12*T01 + c22*T02;
    float v0 = c00*T10 + c01*T11 + c02*T12;
    float v1 = c01*T10 + c11*T11 + c12*T12;
    float v2 = c02*T10 + c12*T11 + c22*T12;
    float a  = T00*u0 + T01*u1 + T02*u2 + 0.3f;
    float b  = T10*u0 + T11*u1 + T12*u2;
    float cc = T10*v0 + T11*v1 + T12*v2 + 0.3f;
    float det = a*cc - b*b;
    bool pos_det = det > 0.0f;
    float inv_det = pos_det ? 1.0f/det : 0.0f;
    float conA = cc*inv_det, conB = -b*inv_det, conC = a*inv_det;
    float mid = 0.5f*(a + cc);
    float lam = mid + sqrtf(fmaxf(mid*mid - det, 0.1f));
    bool visible = in_front && pos_det;
    float radius = visible ? ceilf(3.0f * sqrtf(lam)) : 0.0f;
    float op = opac[i];

    g_p0[i] = make_float4(gx, gy, radius, visible ? op : 0.0f);
    g_p1[i] = make_float4(conA, conB, conC, depth);
    g_dk[i] = __float_as_uint(depth);

    // Packed tile range, widened by construction (floor on low end incl. the
    // -7px tile extent, ceil on high end) => exact superset of overlap set.
    float c0f = fminf(fmaxf(floorf((gx - radius - 7.0f) * 0.125f), 0.0f), 255.0f);
    float c1f = fminf(fmaxf(ceilf ((gx + radius) * 0.125f), 0.0f), 255.0f);
    float r0f = fminf(fmaxf(floorf((gy - radius - 7.0f) * 0.125f), 0.0f), 255.0f);
    float r1f = fminf(fmaxf(ceilf ((gy + radius) * 0.125f), 0.0f), 255.0f);
    unsigned rng = visible
        ? ((unsigned)c0f | ((unsigned)c1f << 8) | ((unsigned)r0f << 16) | ((unsigned)r1f << 24))
        : 0x000000ffu;   // c0=255 => never passes
    g_rng[i] = rng;

    out[3*NPIX + i]            = radius;
    out[3*NPIX + NG + i]       = (radius > 0.0f) ? 1.0f : 0.0f;
    out[3*NPIX + 2*NG + 2*i]   = gx;
    out[3*NPIX + 2*NG + 2*i+1] = gy;
}

// One block per 8x8 tile, 512 threads = 64 pixels x 8 depth segments.
// Phase 1: cull via packed tile-range (1 LDG.32 + byte compares); fetch f0/key
//          only for passing gaussians. Compaction preserves gid order.
// Phase 2: rank-by-counting depth sort. Key = depth_bits<<20 | gid<<10 | slot.
// Phase 3: segmented front-to-back blend; 8 partials composed associatively.
__global__ void __launch_bounds__(NTHR) render_kernel(const float* __restrict__ bg,
                                                      float* __restrict__ out)
{
    __shared__ float4 s_f0[NG];
    __shared__ unsigned long long s_key[NG];
    __shared__ unsigned long long s_srt[NG];
    __shared__ float4 s_part[NSEG][64];
    __shared__ int    s_wcnt[32];
    __shared__ int    s_woff[32];
    __shared__ int    s_count;
    int lid  = threadIdx.x;
    int pixl = lid & 63;
    int seg  = lid >> 6;
    unsigned tx = blockIdx.x, ty = blockIdx.y;
    int warp = lid >> 5, lane = lid & 31;

    // ---- Phase 1: range-based cull + compact (slot order == gid order) ----
    unsigned m[2];
    bool pass[2];
    #pragma unroll
    for (int c = 0; c < 2; c++) {
        unsigned rg = g_rng[c*NTHR + lid];
        pass[c] = ((rg & 0xffu) <= tx) && (((rg >> 8) & 0xffu) >= tx)
               && (((rg >> 16) & 0xffu) <= ty) && ((rg >> 24) >= ty);
        m[c] = __ballot_sync(0xffffffffu, pass[c]);
        if (lane == 0) s_wcnt[c*16 + warp] = __popc(m[c]);
    }
    __syncthreads();
    if (warp == 0) {
        int v = s_wcnt[lane];
        int s = v;
        #pragma unroll
        for (int d = 1; d < 32; d <<= 1) {
            int n = __shfl_up_sync(0xffffffffu, s, d);
            if (lane >= d) s += n;
        }
        s_woff[lane] = s - v;
        if (lane == 31) s_count = s;
    }
    __syncthreads();
    unsigned lmask = (1u << lane) - 1u;
    #pragma unroll
    for (int c = 0; c < 2; c++) {
        if (pass[c]) {
            int gid  = c*NTHR + lid;
            int slot = s_woff[c*16 + warp] + __popc(m[c] & lmask);
            s_f0[slot] = g_p0[gid];          // L1-resident (16KB total)
            s_key[slot] = ((unsigned long long)g_dk[gid] << 20)
                        | ((unsigned long long)gid << 10)
                        | (unsigned long long)slot;
        }
    }
    __syncthreads();
    int count = s_count;

    // ---- Phase 2: rank-by-counting sort (keys unique) ----
    for (int s = lid; s < count; s += NTHR) {
        unsigned long long k = s_key[s];
        int r = 0;
        for (int j = 0; j < count; j++)      // block-wide LDS broadcast
            r += (s_key[j] < k) ? 1 : 0;
        s_srt[r] = k;
    }
    __syncthreads();

    // ---- Phase 3: segmented front-to-back blend ----
    int L   = (count + NSEG - 1) / NSEG;
    int beg = seg * L;
    int end = min(beg + L, count);
    float fpx = (float)(tx*TS + (pixl & 7)), fpy = (float)(ty*TS + (pixl >> 3));
    float T = 1.0f, Cr = 0.0f, Cg = 0.0f, Cb = 0.0f;
    for (int i = beg; i < end; i++) {
        if ((i & 15) == 0 && !__ballot_sync(0xffffffffu, T > 6.1e-5f)) break;
        unsigned long long key = s_srt[i];
        float4 f0 = s_f0[(int)(key & 1023ULL)];
        float ddx = f0.x - fpx, ddy = f0.y - fpy;
        if (fabsf(ddx) <= f0.z && fabsf(ddy) <= f0.z) {
            int gid = (int)((key >> 10) & 1023ULL);
            float4 f1 = __ldg(&g_p1[gid]);   // uniform -> L1 broadcast
            float power = -0.5f*(f1.x*ddx*ddx + f1.z*ddy*ddy) - f1.y*ddx*ddy;
            if (power <= 0.0f) {
                float alpha = fminf(0.99f, f0.w * __expf(power));
                if (alpha >= (1.0f/255.0f)) {
                    float4 f2 = __ldg(&g_p2[gid]);
                    float w = alpha * T;
                    Cr += w*f2.x; Cg += w*f2.y; Cb += w*f2.z;
                    T *= (1.0f - alpha);
                }
            }
        }
    }
    s_part[seg][pixl] = make_float4(Cr, Cg, Cb, T);
    __syncthreads();

    if (lid < 64) {
        float cr = 0.0f, cg = 0.0f, cb = 0.0f, tt = 1.0f;
        #pragma unroll
        for (int s = 0; s < NSEG; s++) {
            float4 p = s_part[s][lid];
            cr += tt*p.x; cg += tt*p.y; cb += tt*p.z;
            tt *= p.w;
        }
        int px = tx*TS + (lid & 7);
        int py = ty*TS + (lid >> 3);
        int pix = py*IMGW + px;
        out[pix]          = cr + tt*bg[0];
        out[NPIX + pix]   = cg + tt*bg[1];
        out[2*NPIX + pix] = cb + tt*bg[2];
    }
}

extern "C" void kernel_launch(void* const* d_in, const int* in_sizes, int n_in,
                              void* d_out, int out_size)
{
    const float* means3D    = (const float*)d_in[0];
    const float* scales     = (const float*)d_in[1];
    const float* rotations  = (const float*)d_in[2];
    const float* opacities  = (const float*)d_in[3];
    const float* shs        = (const float*)d_in[4];
    const float* viewmatrix = (const float*)d_in[5];
    const float* projmatrix = (const float*)d_in[6];
    const float* campos     = (const float*)d_in[7];
    const float* bg_color   = (const float*)d_in[8];
    float* out = (float*)d_out;

    preprocess_kernel<<<32, 64>>>(means3D, scales, rotations, opacities, shs,
                                  viewmatrix, projmatrix, campos, out);
    render_kernel<<<dim3(IMGW/TS, IMGH/TS), dim3(NTHR)>>>(bg_color, out);
}

// round 11
// speedup vs baseline: 1.0872x; 1.0872x over previous
#include <cuda_runtime.h>

#define NG   1024
#define IMGW 192
#define IMGH 192
#define NPIX (IMGW*IMGH)
#define TS   8          // tile size
#define NSEG 8          // depth segments per pixel
#define NTHR 512        // 64 pixels x 8 segments

// Per-gaussian records:
//  p0 = {gx, gy, radius, opacity_eff (0 if invisible)}
//  p1 = {conA, conB, conC, depth}
//  p2 = {colR, colG, colB, 0}
//  rng = packed TIGHT tile range c0|c1<<8|r0<<16|r1<<24 (empty if invisible)
//  dk  = depth bits (for sort key)
__device__ float4 g_p0[NG], g_p1[NG], g_p2[NG];
__device__ unsigned g_rng[NG], g_dk[NG];

// 32 blocks x 64 threads. Blocks 0-15: geometry. Blocks 16-31: SH color.
__global__ void __launch_bounds__(64) preprocess_kernel(
                                  const float* __restrict__ means,
                                  const float* __restrict__ scales,
                                  const float* __restrict__ rots,
                                  const float* __restrict__ opac,
                                  const float* __restrict__ shs,
                                  const float* __restrict__ view,
                                  const float* __restrict__ proj,
                                  const float* __restrict__ campos,
                                  float* __restrict__ out)
{
    int bid = blockIdx.x;
    if (bid >= 16) {
        // ---------------- color half ----------------
        int i = (bid - 16) * 64 + threadIdx.x;
        float mx = means[3*i], my = means[3*i+1], mz = means[3*i+2];
        float4 t[12];
        const float4* sh4 = reinterpret_cast<const float4*>(shs + i*48);
        #pragma unroll
        for (int w = 0; w < 12; w++) t[w] = __ldg(sh4 + w);

        float dxc = mx - campos[0], dyc = my - campos[1], dzc = mz - campos[2];
        float inv = rsqrtf(dxc*dxc + dyc*dyc + dzc*dzc);
        float x = dxc*inv, y = dyc*inv, z = dzc*inv;
        float xx = x*x, yy = y*y, zz = z*z, xy = x*y, yz = y*z, xz = x*z;
        float bas[16];
        bas[0]  = 0.28209479177387814f;
        bas[1]  = -0.4886025119029199f * y;
        bas[2]  =  0.4886025119029199f * z;
        bas[3]  = -0.4886025119029199f * x;
        bas[4]  =  1.0925484305920792f * xy;
        bas[5]  = -1.0925484305920792f * yz;
        bas[6]  =  0.31539156525252005f * (2.0f*zz - xx - yy);
        bas[7]  = -1.0925484305920792f * xz;
        bas[8]  =  0.5462742152960396f * (xx - yy);
        bas[9]  = -0.5900435899266435f * y * (3.0f*xx - yy);
        bas[10] =  2.890611442640554f  * xy * z;
        bas[11] = -0.4570457994644658f * y * (4.0f*zz - xx - yy);
        bas[12] =  0.3731763325901154f * z * (2.0f*zz - 3.0f*xx - 3.0f*yy);
        bas[13] = -0.4570457994644658f * x * (4.0f*zz - xx - yy);
        bas[14] =  1.445305721320277f  * z * (xx - yy);
        bas[15] = -0.5900435899266435f * x * (xx - yy - 3.0f*zz);

        float col[3] = {0.5f, 0.5f, 0.5f};
        #pragma unroll
        for (int w = 0; w < 12; w++) {
            float v[4] = {t[w].x, t[w].y, t[w].z, t[w].w};
            #pragma unroll
            for (int j = 0; j < 4; j++) {
                const int flat = 4*w + j;
                col[flat % 3] += bas[flat / 3] * v[j];
            }
        }
        g_p2[i] = make_float4(fmaxf(col[0], 0.0f), fmaxf(col[1], 0.0f),
                              fmaxf(col[2], 0.0f), 0.0f);
        return;
    }

    // ---------------- geometry half ----------------
    int i = bid * 64 + threadIdx.x;
    float mx = means[3*i], my = means[3*i+1], mz = means[3*i+2];

    float4 q = __ldg(reinterpret_cast<const float4*>(rots) + i);
    float qr = q.x, qx = q.y, qy = q.z, qz = q.w;
    float sx = scales[3*i], sy = scales[3*i+1], sz = scales[3*i+2];
    float R00 = 1.0f-2.0f*(qy*qy+qz*qz), R01 = 2.0f*(qx*qy-qr*qz), R02 = 2.0f*(qx*qz+qr*qy);
    float R10 = 2.0f*(qx*qy+qr*qz), R11 = 1.0f-2.0f*(qx*qx+qz*qz), R12 = 2.0f*(qy*qz-qr*qx);
    float R20 = 2.0f*(qx*qz-qr*qy), R21 = 2.0f*(qy*qz+qr*qx), R22 = 1.0f-2.0f*(qx*qx+qy*qy);
    float M00=R00*sx, M01=R01*sy, M02=R02*sz;
    float M10=R10*sx, M11=R11*sy, M12=R12*sz;
    float M20=R20*sx, M21=R21*sy, M22=R22*sz;
    float c00 = M00*M00+M01*M01+M02*M02;
    float c01 = M00*M10+M01*M11+M02*M12;
    float c02 = M00*M20+M01*M21+M02*M22;
    float c11 = M10*M10+M11*M11+M12*M12;
    float c12 = M10*M20+M11*M21+M12*M22;
    float c22 = M20*M20+M21*M21+M22*M22;

    float pvx = view[0]*mx + view[1]*my + view[2]*mz + view[3];
    float pvy = view[4]*mx + view[5]*my + view[6]*mz + view[7];
    float pvz = view[8]*mx + view[9]*my + view[10]*mz + view[11];
    float phx = proj[0]*mx + proj[1]*my + proj[2]*mz + proj[3];
    float phy = proj[4]*mx + proj[5]*my + proj[6]*mz + proj[7];
    float phw = proj[12]*mx + proj[13]*my + proj[14]*mz + proj[15];
    float invw = 1.0f / (phw + 1e-7f);
    float gx = ((phx*invw + 1.0f) * (float)IMGW - 1.0f) * 0.5f;
    float gy = ((phy*invw + 1.0f) * (float)IMGH - 1.0f) * 0.5f;
    float depth = pvz;
    bool in_front = depth > 0.2f;
    float tz = in_front ? depth : 1.0f;
    const float lim = 1.3f * 0.5f;
    float txv = fminf(fmaxf(pvx/tz, -lim), lim) * tz;
    float tyv = fminf(fmaxf(pvy/tz, -lim), lim) * tz;
    const float fx = (float)IMGW / (2.0f*0.5f);
    const float fy = (float)IMGH / (2.0f*0.5f);
    float J00 = fx/tz, J02 = -fx*txv/(tz*tz);
    float J11 = fy/tz, J12 = -fy*tyv/(tz*tz);
    float T00 = J00*view[0] + J02*view[8];
    float T01 = J00*view[1] + J02*view[9];
    float T02 = J00*view[2] + J02*view[10];
    float T10 = J11*view[4] + J12*view[8];
    float T11 = J11*view[5] + J12*view[9];
    float T12 = J11*view[6] + J12*view[10];
    float u0 = c00*T00 + c01*T01 + c02*T02;
    float u1 = c01*T00 + c11*T01 + c12*T02;
    float u2 = c02*T00 + c12*T01 + c22*T02;
    float v0 = c00*T10 + c01*T11 + c02*T12;
    float v1 = c01*T10 + c11*T11 + c12*T12;
    float v2 = c02*T10 + c12*T11 + c22*T12;
    float a  = T00*u0 + T01*u1 + T02*u2 + 0.3f;
    float b  = T10*u0 + T11*u1 + T12*u2;
    float cc = T10*v0 + T11*v1 + T12*v2 + 0.3f;
    float det = a*cc - b*b;
    bool pos_det = det > 0.0f;
    float inv_det = pos_det ? 1.0f/det : 0.0f;
    float conA = cc*inv_det, conB = -b*inv_det, conC = a*inv_det;
    float mid = 0.5f*(a + cc);
    float lam = mid + sqrtf(fmaxf(mid*mid - det, 0.1f));
    bool visible = in_front && pos_det;
    float radius = visible ? ceilf(3.0f * sqrtf(lam)) : 0.0f;
    float op = opac[i];

    g_p0[i] = make_float4(gx, gy, radius, visible ? op : 0.0f);
    g_p1[i] = make_float4(conA, conB, conC, depth);
    g_dk[i] = __float_as_uint(depth);

    // TIGHT tile range (eps-widened superset of the exact bbox test):
    // tile c overlaps iff c >= (gx-r-7)/8 and c <= (gx+r)/8.
    float c0f = fminf(fmaxf(ceilf ((gx - radius - 7.0f) * 0.125f - 1e-4f), 0.0f), 255.0f);
    float c1f = fminf(fmaxf(floorf((gx + radius) * 0.125f + 1e-4f), -1.0f), 255.0f);
    float r0f = fminf(fmaxf(ceilf ((gy - radius - 7.0f) * 0.125f - 1e-4f), 0.0f), 255.0f);
    float r1f = fminf(fmaxf(floorf((gy + radius) * 0.125f + 1e-4f), -1.0f), 255.0f);
    unsigned rng;
    if (visible && c1f >= c0f && r1f >= r0f)
        rng = (unsigned)c0f | ((unsigned)c1f << 8) | ((unsigned)r0f << 16) | ((unsigned)r1f << 24);
    else
        rng = 0x000000ffu;   // c0=255 > any c1 => never passes
    g_rng[i] = rng;

    out[3*NPIX + i]            = radius;
    out[3*NPIX + NG + i]       = (radius > 0.0f) ? 1.0f : 0.0f;
    out[3*NPIX + 2*NG + 2*i]   = gx;
    out[3*NPIX + 2*NG + 2*i+1] = gy;
}

// One block per 8x8 tile, 512 threads = 64 pixels x 8 depth segments.
// Phase 1: cull via packed tile-range (1 LDG.32 + byte compares); fetch f0/key
//          only for passing gaussians. Compaction preserves gid order.
// Phase 2: rank-by-counting depth sort. Key = depth_bits<<20 | gid<<10 | slot.
// Phase 3: segmented front-to-back blend; 8 partials composed associatively.
__global__ void __launch_bounds__(NTHR) render_kernel(const float* __restrict__ bg,
                                                      float* __restrict__ out)
{
    __shared__ float4 s_f0[NG];
    __shared__ unsigned long long s_key[NG];
    __shared__ unsigned long long s_srt[NG];
    __shared__ float4 s_part[NSEG][64];
    __shared__ int    s_wcnt[32];
    __shared__ int    s_woff[32];
    __shared__ int    s_count;
    int lid  = threadIdx.x;
    int pixl = lid & 63;
    int seg  = lid >> 6;
    unsigned tx = blockIdx.x, ty = blockIdx.y;
    int warp = lid >> 5, lane = lid & 31;

    // ---- Phase 1: range-based cull + compact (slot order == gid order) ----
    unsigned m[2];
    bool pass[2];
    #pragma unroll
    for (int c = 0; c < 2; c++) {
        unsigned rg = g_rng[c*NTHR + lid];
        pass[c] = ((rg & 0xffu) <= tx) && (((rg >> 8) & 0xffu) >= tx)
               && (((rg >> 16) & 0xffu) <= ty) && ((rg >> 24) >= ty);
        m[c] = __ballot_sync(0xffffffffu, pass[c]);
        if (lane == 0) s_wcnt[c*16 + warp] = __popc(m[c]);
    }
    __syncthreads();
    if (warp == 0) {
        int v = s_wcnt[lane];
        int s = v;
        #pragma unroll
        for (int d = 1; d < 32; d <<= 1) {
            int n = __shfl_up_sync(0xffffffffu, s, d);
            if (lane >= d) s += n;
        }
        s_woff[lane] = s - v;
        if (lane == 31) s_count = s;
    }
    __syncthreads();
    unsigned lmask = (1u << lane) - 1u;
    #pragma unroll
    for (int c = 0; c < 2; c++) {
        if (pass[c]) {
            int gid  = c*NTHR + lid;
            int slot = s_woff[c*16 + warp] + __popc(m[c] & lmask);
            s_f0[slot] = g_p0[gid];          // L1-resident (16KB total)
            s_key[slot] = ((unsigned long long)g_dk[gid] << 20)
                        | ((unsigned long long)gid << 10)
                        | (unsigned long long)slot;
        }
    }
    __syncthreads();
    int count = s_count;

    // ---- Phase 2: rank-by-counting sort (keys unique) ----
    for (int s = lid; s < count; s += NTHR) {
        unsigned long long k = s_key[s];
        int r = 0;
        for (int j = 0; j < count; j++)      // block-wide LDS broadcast
            r += (s_key[j] < k) ? 1 : 0;
        s_srt[r] = k;
    }
    __syncthreads();

    // ---- Phase 3: segmented front-to-back blend ----
    int L   = (count + NSEG - 1) / NSEG;
    int beg = seg * L;
    int end = min(beg + L, count);
    float fpx = (float)(tx*TS + (pixl & 7)), fpy = (float)(ty*TS + (pixl >> 3));
    float T = 1.0f, Cr = 0.0f, Cg = 0.0f, Cb = 0.0f;
    for (int i = beg; i < end; i++) {
        if ((i & 15) == 0 && !__ballot_sync(0xffffffffu, T > 6.1e-5f)) break;
        unsigned long long key = s_srt[i];
        float4 f0 = s_f0[(int)(key & 1023ULL)];
        float ddx = f0.x - fpx, ddy = f0.y - fpy;
        if (fabsf(ddx) <= f0.z && fabsf(ddy) <= f0.z) {
            int gid = (int)((key >> 10) & 1023ULL);
            float4 f1 = __ldg(&g_p1[gid]);   // uniform -> L1 broadcast
            float power = -0.5f*(f1.x*ddx*ddx + f1.z*ddy*ddy) - f1.y*ddx*ddy;
            if (power <= 0.0f) {
                float alpha = fminf(0.99f, f0.w * __expf(power));
                if (alpha >= (1.0f/255.0f)) {
                    float4 f2 = __ldg(&g_p2[gid]);
                    float w = alpha * T;
                    Cr += w*f2.x; Cg += w*f2.y; Cb += w*f2.z;
                    T *= (1.0f - alpha);
                }
            }
        }
    }
    s_part[seg][pixl] = make_float4(Cr, Cg, Cb, T);
    __syncthreads();

    if (lid < 64) {
        float cr = 0.0f, cg = 0.0f, cb = 0.0f, tt = 1.0f;
        #pragma unroll
        for (int s = 0; s < NSEG; s++) {
            float4 p = s_part[s][lid];
            cr += tt*p.x; cg += tt*p.y; cb += tt*p.z;
            tt *= p.w;
        }
        int px = tx*TS + (lid & 7);
        int py = ty*TS + (lid >> 3);
        int pix = py*IMGW + px;
        out[pix]          = cr + tt*bg[0];
        out[NPIX + pix]   = cg + tt*bg[1];
        out[2*NPIX + pix] = cb + tt*bg[2];
    }
}

extern "C" void kernel_launch(void* const* d_in, const int* in_sizes, int n_in,
                              void* d_out, int out_size)
{
    const float* means3D    = (const float*)d_in[0];
    const float* scales     = (const float*)d_in[1];
    const float* rotations  = (const float*)d_in[2];
    const float* opacities  = (const float*)d_in[3];
    const float* shs        = (const float*)d_in[4];
    const float* viewmatrix = (const float*)d_in[5];
    const float* projmatrix = (const float*)d_in[6];
    const float* campos     = (const float*)d_in[7];
    const float* bg_color   = (const float*)d_in[8];
    float* out = (float*)d_out;

    preprocess_kernel<<<32, 64>>>(means3D, scales, rotations, opacities, shs,
                                  viewmatrix, projmatrix, campos, out);
    render_kernel<<<dim3(IMGW/TS, IMGH/TS), dim3(NTHR)>>>(bg_color, out);
}

// round 12
// speedup vs baseline: 1.2362x; 1.1370x over previous
#include <cuda_runtime.h>

#define NG   1024
#define IMGW 192
#define IMGH 192
#define NPIX (IMGW*IMGH)
#define TS   8          // tile size
#define NSEG 8          // depth segments per pixel
#define NTHR 512        // 64 pixels x 8 segments

// Dynamic shared layout (bytes):
//  s_f0   float4[NG]   @ 0        16384   {gx,gy,radius,op}
//  s_c1   float4[NG]   @ 16384    16384   {conA,conB,conC,colR}
//  s_c2   float2[NG]   @ 32768     8192   {colG,colB}
//  s_dep  float [NG]   @ 40960     4096   depth
//  s_ord  ushort[NG]   @ 45056     2048   sorted order -> slot
//  s_part float4[8][64]@ 47104     8192
#define SMEM_BYTES 55296

// Per-gaussian records:
//  p0 = {gx, gy, radius, opacity_eff (0 if invisible)}
//  p1 = {conA, conB, conC, depth}
//  p2 = {colR, colG, colB, 0}
//  rng = packed TIGHT tile range c0|c1<<8|r0<<16|r1<<24 (empty if invisible)
__device__ float4 g_p0[NG], g_p1[NG], g_p2[NG];
__device__ unsigned g_rng[NG];

// 32 blocks x 64 threads. Blocks 0-15: geometry. Blocks 16-31: SH color.
__global__ void __launch_bounds__(64) preprocess_kernel(
                                  const float* __restrict__ means,
                                  const float* __restrict__ scales,
                                  const float* __restrict__ rots,
                                  const float* __restrict__ opac,
                                  const float* __restrict__ shs,
                                  const float* __restrict__ view,
                                  const float* __restrict__ proj,
                                  const float* __restrict__ campos,
                                  float* __restrict__ out)
{
    int bid = blockIdx.x;
    if (bid >= 16) {
        // ---------------- color half ----------------
        int i = (bid - 16) * 64 + threadIdx.x;
        float mx = means[3*i], my = means[3*i+1], mz = means[3*i+2];
        float4 t[12];
        const float4* sh4 = reinterpret_cast<const float4*>(shs + i*48);
        #pragma unroll
        for (int w = 0; w < 12; w++) t[w] = __ldg(sh4 + w);

        float dxc = mx - campos[0], dyc = my - campos[1], dzc = mz - campos[2];
        float inv = rsqrtf(dxc*dxc + dyc*dyc + dzc*dzc);
        float x = dxc*inv, y = dyc*inv, z = dzc*inv;
        float xx = x*x, yy = y*y, zz = z*z, xy = x*y, yz = y*z, xz = x*z;
        float bas[16];
        bas[0]  = 0.28209479177387814f;
        bas[1]  = -0.4886025119029199f * y;
        bas[2]  =  0.4886025119029199f * z;
        bas[3]  = -0.4886025119029199f * x;
        bas[4]  =  1.0925484305920792f * xy;
        bas[5]  = -1.0925484305920792f * yz;
        bas[6]  =  0.31539156525252005f * (2.0f*zz - xx - yy);
        bas[7]  = -1.0925484305920792f * xz;
        bas[8]  =  0.5462742152960396f * (xx - yy);
        bas[9]  = -0.5900435899266435f * y * (3.0f*xx - yy);
        bas[10] =  2.890611442640554f  * xy * z;
        bas[11] = -0.4570457994644658f * y * (4.0f*zz - xx - yy);
        bas[12] =  0.3731763325901154f * z * (2.0f*zz - 3.0f*xx - 3.0f*yy);
        bas[13] = -0.4570457994644658f * x * (4.0f*zz - xx - yy);
        bas[14] =  1.445305721320277f  * z * (xx - yy);
        bas[15] = -0.5900435899266435f * x * (xx - yy - 3.0f*zz);

        float col[3] = {0.5f, 0.5f, 0.5f};
        #pragma unroll
        for (int w = 0; w < 12; w++) {
            float v[4] = {t[w].x, t[w].y, t[w].z, t[w].w};
            #pragma unroll
            for (int j = 0; j < 4; j++) {
                const int flat = 4*w + j;
                col[flat % 3] += bas[flat / 3] * v[j];
            }
        }
        g_p2[i] = make_float4(fmaxf(col[0], 0.0f), fmaxf(col[1], 0.0f),
                              fmaxf(col[2], 0.0f), 0.0f);
        return;
    }

    // ---------------- geometry half ----------------
    int i = bid * 64 + threadIdx.x;
    float mx = means[3*i], my = means[3*i+1], mz = means[3*i+2];

    float4 q = __ldg(reinterpret_cast<const float4*>(rots) + i);
    float qr = q.x, qx = q.y, qy = q.z, qz = q.w;
    float sx = scales[3*i], sy = scales[3*i+1], sz = scales[3*i+2];
    float R00 = 1.0f-2.0f*(qy*qy+qz*qz), R01 = 2.0f*(qx*qy-qr*qz), R02 = 2.0f*(qx*qz+qr*qy);
    float R10 = 2.0f*(qx*qy+qr*qz), R11 = 1.0f-2.0f*(qx*qx+qz*qz), R12 = 2.0f*(qy*qz-qr*qx);
    float R20 = 2.0f*(qx*qz-qr*qy), R21 = 2.0f*(qy*qz+qr*qx), R22 = 1.0f-2.0f*(qx*qx+qy*qy);
    float M00=R00*sx, M01=R01*sy, M02=R02*sz;
    float M10=R10*sx, M11=R11*sy, M12=R12*sz;
    float M20=R20*sx, M21=R21*sy, M22=R22*sz;
    float c00 = M00*M00+M01*M01+M02*M02;
    float c01 = M00*M10+M01*M11+M02*M12;
    float c02 = M00*M20+M01*M21+M02*M22;
    float c11 = M10*M10+M11*M11+M12*M12;
    float c12 = M10*M20+M11*M21+M12*M22;
    float c22 = M20*M20+M21*M21+M22*M22;

    float pvx = view[0]*mx + view[1]*my + view[2]*mz + view[3];
    float pvy = view[4]*mx + view[5]*my + view[6]*mz + view[7];
    float pvz = view[8]*mx + view[9]*my + view[10]*mz + view[11];
    float phx = proj[0]*mx + proj[1]*my + proj[2]*mz + proj[3];
    float phy = proj[4]*mx + proj[5]*my + proj[6]*mz + proj[7];
    float phw = proj[12]*mx + proj[13]*my + proj[14]*mz + proj[15];
    float invw = 1.0f / (phw + 1e-7f);
    float gx = ((phx*invw + 1.0f) * (float)IMGW - 1.0f) * 0.5f;
    float gy = ((phy*invw + 1.0f) * (float)IMGH - 1.0f) * 0.5f;
    float depth = pvz;
    bool in_front = depth > 0.2f;
    float tz = in_front ? depth : 1.0f;
    const float lim = 1.3f * 0.5f;
    float txv = fminf(fmaxf(pvx/tz, -lim), lim) * tz;
    float tyv = fminf(fmaxf(pvy/tz, -lim), lim) * tz;
    const float fx = (float)IMGW / (2.0f*0.5f);
    const float fy = (float)IMGH / (2.0f*0.5f);
    float J00 = fx/tz, J02 = -fx*txv/(tz*tz);
    float J11 = fy/tz, J12 = -fy*tyv/(tz*tz);
    float T00 = J00*view[0] + J02*view[8];
    float T01 = J00*view[1] + J02*view[9];
    float T02 = J00*view[2] + J02*view[10];
    float T10 = J11*view[4] + J12*view[8];
    float T11 = J11*view[5] + J12*view[9];
    float T12 = J11*view[6] + J12*view[10];
    float u0 = c00*T00 + c01*T01 + c02*T02;
    float u1 = c01*T00 + c11*T01 + c12*T02;
    float u2 = c02*T00 + c12*T01 + c22*T02;
    float v0 = c00*T10 + c01*T11 + c02*T12;
    float v1 = c01*T10 + c11*T11 + c12*T12;
    float v2 = c02*T10 + c12*T11 + c22*T12;
    float a  = T00*u0 + T01*u1 + T02*u2 + 0.3f;
    float b  = T10*u0 + T11*u1 + T12*u2;
    float cc = T10*v0 + T11*v1 + T12*v2 + 0.3f;
    float det = a*cc - b*b;
    bool pos_det = det > 0.0f;
    float inv_det = pos_det ? 1.0f/det : 0.0f;
    float conA = cc*inv_det, conB = -b*inv_det, conC = a*inv_det;
    float mid = 0.5f*(a + cc);
    float lam = mid + sqrtf(fmaxf(mid*mid - det, 0.1f));
    bool visible = in_front && pos_det;
    float radius = visible ? ceilf(3.0f * sqrtf(lam)) : 0.0f;
    float op = opac[i];

    g_p0[i] = make_float4(gx, gy, radius, visible ? op : 0.0f);
    g_p1[i] = make_float4(conA, conB, conC, depth);

    // TIGHT tile range (eps-widened superset of the exact bbox test).
    float c0f = fminf(fmaxf(ceilf ((gx - radius - 7.0f) * 0.125f - 1e-4f), 0.0f), 255.0f);
    float c1f = fminf(fmaxf(floorf((gx + radius) * 0.125f + 1e-4f), -1.0f), 255.0f);
    float r0f = fminf(fmaxf(ceilf ((gy - radius - 7.0f) * 0.125f - 1e-4f), 0.0f), 255.0f);
    float r1f = fminf(fmaxf(floorf((gy + radius) * 0.125f + 1e-4f), -1.0f), 255.0f);
    unsigned rng;
    if (visible && c1f >= c0f && r1f >= r0f)
        rng = (unsigned)c0f | ((unsigned)c1f << 8) | ((unsigned)r0f << 16) | ((unsigned)r1f << 24);
    else
        rng = 0x000000ffu;   // c0=255 > any c1 => never passes
    g_rng[i] = rng;

    out[3*NPIX + i]            = radius;
    out[3*NPIX + NG + i]       = (radius > 0.0f) ? 1.0f : 0.0f;
    out[3*NPIX + 2*NG + 2*i]   = gx;
    out[3*NPIX + 2*NG + 2*i+1] = gy;
}

// One block per 8x8 tile, 512 threads = 64 pixels x 8 depth segments.
// Phase 1: cull via packed tile-range; compaction copies position, conic AND
//          color into shared (blend chain never touches L2).
// Phase 2: rank-by-counting sort on (depth, slot) -- unique, stable tie-break.
// Phase 3: segmented front-to-back blend entirely from shared.
__global__ void __launch_bounds__(NTHR) render_kernel(const float* __restrict__ bg,
                                                      float* __restrict__ out)
{
    extern __shared__ char dsm[];
    float4*  s_f0  = reinterpret_cast<float4*>(dsm);            // [NG]
    float4*  s_c1  = reinterpret_cast<float4*>(dsm + 16384);    // [NG]
    float2*  s_c2  = reinterpret_cast<float2*>(dsm + 32768);    // [NG]
    float*   s_dep = reinterpret_cast<float*>(dsm + 40960);     // [NG]
    unsigned short* s_ord = reinterpret_cast<unsigned short*>(dsm + 45056); // [NG]
    float4*  s_part = reinterpret_cast<float4*>(dsm + 47104);   // [NSEG*64]
    __shared__ int s_wcnt[32];
    __shared__ int s_woff[32];
    __shared__ int s_count;

    int lid  = threadIdx.x;
    int pixl = lid & 63;
    int seg  = lid >> 6;
    unsigned tx = blockIdx.x, ty = blockIdx.y;
    int warp = lid >> 5, lane = lid & 31;

    // ---- Phase 1: range-based cull + compact (slot order == gid order) ----
    unsigned m[2];
    bool pass[2];
    #pragma unroll
    for (int c = 0; c < 2; c++) {
        unsigned rg = g_rng[c*NTHR + lid];
        pass[c] = ((rg & 0xffu) <= tx) && (((rg >> 8) & 0xffu) >= tx)
               && (((rg >> 16) & 0xffu) <= ty) && ((rg >> 24) >= ty);
        m[c] = __ballot_sync(0xffffffffu, pass[c]);
        if (lane == 0) s_wcnt[c*16 + warp] = __popc(m[c]);
    }
    __syncthreads();
    if (warp == 0) {
        int v = s_wcnt[lane];
        int s = v;
        #pragma unroll
        for (int d = 1; d < 32; d <<= 1) {
            int n = __shfl_up_sync(0xffffffffu, s, d);
            if (lane >= d) s += n;
        }
        s_woff[lane] = s - v;
        if (lane == 31) s_count = s;
    }
    __syncthreads();
    unsigned lmask = (1u << lane) - 1u;
    #pragma unroll
    for (int c = 0; c < 2; c++) {
        if (pass[c]) {
            int gid  = c*NTHR + lid;
            int slot = s_woff[c*16 + warp] + __popc(m[c] & lmask);
            float4 f1 = g_p1[gid];           // coalesced under predicate
            float4 f2 = g_p2[gid];
            s_f0[slot]  = g_p0[gid];
            s_c1[slot]  = make_float4(f1.x, f1.y, f1.z, f2.x);
            s_c2[slot]  = make_float2(f2.y, f2.z);
            s_dep[slot] = f1.w;
        }
    }
    __syncthreads();
    int count = s_count;

    // ---- Phase 2: rank-by-counting sort on (depth, slot) ----
    for (int s = lid; s < count; s += NTHR) {
        float k = s_dep[s];
        int r = 0;
        for (int j = 0; j < count; j++) {    // block-wide LDS broadcast
            float kj = s_dep[j];
            r += (kj < k || (kj == k && j < s)) ? 1 : 0;
        }
        s_ord[r] = (unsigned short)s;
    }
    __syncthreads();

    // ---- Phase 3: segmented front-to-back blend (all shared) ----
    int L   = (count + NSEG - 1) / NSEG;
    int beg = seg * L;
    int end = min(beg + L, count);
    float fpx = (float)(tx*TS + (pixl & 7)), fpy = (float)(ty*TS + (pixl >> 3));
    float T = 1.0f, Cr = 0.0f, Cg = 0.0f, Cb = 0.0f;
    for (int i = beg; i < end; i++) {
        if ((i & 15) == 0 && !__ballot_sync(0xffffffffu, T > 6.1e-5f)) break;
        int slot = s_ord[i];                 // LDS broadcast
        float4 f0 = s_f0[slot];
        float ddx = f0.x - fpx, ddy = f0.y - fpy;
        if (fabsf(ddx) <= f0.z && fabsf(ddy) <= f0.z) {
            float4 c1 = s_c1[slot];
            float power = -0.5f*(c1.x*ddx*ddx + c1.z*ddy*ddy) - c1.y*ddx*ddy;
            if (power <= 0.0f) {
                float alpha = fminf(0.99f, f0.w * __expf(power));
                if (alpha >= (1.0f/255.0f)) {
                    float2 c2 = s_c2[slot];
                    float w = alpha * T;
                    Cr += w*c1.w; Cg += w*c2.x; Cb += w*c2.y;
                    T *= (1.0f - alpha);
                }
            }
        }
    }
    s_part[seg*64 + pixl] = make_float4(Cr, Cg, Cb, T);
    __syncthreads();

    if (lid < 64) {
        float cr = 0.0f, cg = 0.0f, cb = 0.0f, tt = 1.0f;
        #pragma unroll
        for (int s = 0; s < NSEG; s++) {
            float4 p = s_part[s*64 + lid];
            cr += tt*p.x; cg += tt*p.y; cb += tt*p.z;
            tt *= p.w;
        }
        int px = tx*TS + (lid & 7);
        int py = ty*TS + (lid >> 3);
        int pix = py*IMGW + px;
        out[pix]          = cr + tt*bg[0];
        out[NPIX + pix]   = cg + tt*bg[1];
        out[2*NPIX + pix] = cb + tt*bg[2];
    }
}

extern "C" void kernel_launch(void* const* d_in, const int* in_sizes, int n_in,
                              void* d_out, int out_size)
{
    const float* means3D    = (const float*)d_in[0];
    const float* scales     = (const float*)d_in[1];
    const float* rotations  = (const float*)d_in[2];
    const float* opacities  = (const float*)d_in[3];
    const float* shs        = (const float*)d_in[4];
    const float* viewmatrix = (const float*)d_in[5];
    const float* projmatrix = (const float*)d_in[6];
    const float* campos     = (const float*)d_in[7];
    const float* bg_color   = (const float*)d_in[8];
    float* out = (float*)d_out;

    static int attr_done = 0;
    if (!attr_done) {
        cudaFuncSetAttribute(render_kernel,
                             cudaFuncAttributeMaxDynamicSharedMemorySize,
                             SMEM_BYTES);
        attr_done = 1;
    }

    preprocess_kernel<<<32, 64>>>(means3D, scales, rotations, opacities, shs,
                                  viewmatrix, projmatrix, campos, out);
    render_kernel<<<dim3(IMGW/TS, IMGH/TS), dim3(NTHR), SMEM_BYTES>>>(bg_color, out);
}

// round 13
// speedup vs baseline: 1.3127x; 1.0619x over previous
#include <cuda_runtime.h>

#define NG   1024
#define IMGW 192
#define IMGH 192
#define NPIX (IMGW*IMGH)
#define TS   8          // tile size
#define NSEG 8          // depth segments per pixel
#define NTHR 512        // 64 pixels x 8 segments

// Dynamic shared layout (bytes), all sorted-order after phase 2:
//  s_f0   float4[NG]   @ 0        16384   {gx,gy,radius,op}
//  s_c1   float4[NG]   @ 16384    16384   {conA,conB,conC,colR}
//  s_c2   float2[NG]   @ 32768     8192   {colG,colB}
//  s_dep  float [NG]   @ 40960     4096   depth (slot order)
//  s_gid  ushort[NG]   @ 45056     2048   slot -> gid
//  s_part float4[8][64]@ 47104     8192
#define SMEM_BYTES 55296

// Per-gaussian records:
//  p0 = {gx, gy, radius, opacity_eff (0 if invisible)}
//  p1 = {conA, conB, conC, depth}
//  p2 = {colR, colG, colB, 0}
//  rng = packed TIGHT tile range c0|c1<<8|r0<<16|r1<<24 (empty if invisible)
//  dep = depth (scalar, for cheap phase-1 load)
__device__ float4 g_p0[NG], g_p1[NG], g_p2[NG];
__device__ unsigned g_rng[NG];
__device__ float g_dep[NG];

// 32 blocks x 64 threads. Blocks 0-15: geometry. Blocks 16-31: SH color.
__global__ void __launch_bounds__(64) preprocess_kernel(
                                  const float* __restrict__ means,
                                  const float* __restrict__ scales,
                                  const float* __restrict__ rots,
                                  const float* __restrict__ opac,
                                  const float* __restrict__ shs,
                                  const float* __restrict__ view,
                                  const float* __restrict__ proj,
                                  const float* __restrict__ campos,
                                  float* __restrict__ out)
{
    int bid = blockIdx.x;
    if (bid >= 16) {
        // ---------------- color half ----------------
        int i = (bid - 16) * 64 + threadIdx.x;
        float mx = means[3*i], my = means[3*i+1], mz = means[3*i+2];
        float4 t[12];
        const float4* sh4 = reinterpret_cast<const float4*>(shs + i*48);
        #pragma unroll
        for (int w = 0; w < 12; w++) t[w] = __ldg(sh4 + w);

        float dxc = mx - campos[0], dyc = my - campos[1], dzc = mz - campos[2];
        float inv = rsqrtf(dxc*dxc + dyc*dyc + dzc*dzc);
        float x = dxc*inv, y = dyc*inv, z = dzc*inv;
        float xx = x*x, yy = y*y, zz = z*z, xy = x*y, yz = y*z, xz = x*z;
        float bas[16];
        bas[0]  = 0.28209479177387814f;
        bas[1]  = -0.4886025119029199f * y;
        bas[2]  =  0.4886025119029199f * z;
        bas[3]  = -0.4886025119029199f * x;
        bas[4]  =  1.0925484305920792f * xy;
        bas[5]  = -1.0925484305920792f * yz;
        bas[6]  =  0.31539156525252005f * (2.0f*zz - xx - yy);
        bas[7]  = -1.0925484305920792f * xz;
        bas[8]  =  0.5462742152960396f * (xx - yy);
        bas[9]  = -0.5900435899266435f * y * (3.0f*xx - yy);
        bas[10] =  2.890611442640554f  * xy * z;
        bas[11] = -0.4570457994644658f * y * (4.0f*zz - xx - yy);
        bas[12] =  0.3731763325901154f * z * (2.0f*zz - 3.0f*xx - 3.0f*yy);
        bas[13] = -0.4570457994644658f * x * (4.0f*zz - xx - yy);
        bas[14] =  1.445305721320277f  * z * (xx - yy);
        bas[15] = -0.5900435899266435f * x * (xx - yy - 3.0f*zz);

        float col[3] = {0.5f, 0.5f, 0.5f};
        #pragma unroll
        for (int w = 0; w < 12; w++) {
            float v[4] = {t[w].x, t[w].y, t[w].z, t[w].w};
            #pragma unroll
            for (int j = 0; j < 4; j++) {
                const int flat = 4*w + j;
                col[flat % 3] += bas[flat / 3] * v[j];
            }
        }
        g_p2[i] = make_float4(fmaxf(col[0], 0.0f), fmaxf(col[1], 0.0f),
                              fmaxf(col[2], 0.0f), 0.0f);
#if __CUDA_ARCH__ >= 900
        cudaTriggerProgrammaticLaunchCompletion();
#endif
        return;
    }

    // ---------------- geometry half ----------------
    int i = bid * 64 + threadIdx.x;
    float mx = means[3*i], my = means[3*i+1], mz = means[3*i+2];

    float4 q = __ldg(reinterpret_cast<const float4*>(rots) + i);
    float qr = q.x, qx = q.y, qy = q.z, qz = q.w;
    float sx = scales[3*i], sy = scales[3*i+1], sz = scales[3*i+2];
    float R00 = 1.0f-2.0f*(qy*qy+qz*qz), R01 = 2.0f*(qx*qy-qr*qz), R02 = 2.0f*(qx*qz+qr*qy);
    float R10 = 2.0f*(qx*qy+qr*qz), R11 = 1.0f-2.0f*(qx*qx+qz*qz), R12 = 2.0f*(qy*qz-qr*qx);
    float R20 = 2.0f*(qx*qz-qr*qy), R21 = 2.0f*(qy*qz+qr*qx), R22 = 1.0f-2.0f*(qx*qx+qy*qy);
    float M00=R00*sx, M01=R01*sy, M02=R02*sz;
    float M10=R10*sx, M11=R11*sy, M12=R12*sz;
    float M20=R20*sx, M21=R21*sy, M22=R22*sz;
    float c00 = M00*M00+M01*M01+M02*M02;
    float c01 = M00*M10+M01*M11+M02*M12;
    float c02 = M00*M20+M01*M21+M02*M22;
    float c11 = M10*M10+M11*M11+M12*M12;
    float c12 = M10*M20+M11*M21+M12*M22;
    float c22 = M20*M20+M21*M21+M22*M22;

    float pvx = view[0]*mx + view[1]*my + view[2]*mz + view[3];
    float pvy = view[4]*mx + view[5]*my + view[6]*mz + view[7];
    float pvz = view[8]*mx + view[9]*my + view[10]*mz + view[11];
    float phx = proj[0]*mx + proj[1]*my + proj[2]*mz + proj[3];
    float phy = proj[4]*mx + proj[5]*my + proj[6]*mz + proj[7];
    float phw = proj[12]*mx + proj[13]*my + proj[14]*mz + proj[15];
    float invw = 1.0f / (phw + 1e-7f);
    float gx = ((phx*invw + 1.0f) * (float)IMGW - 1.0f) * 0.5f;
    float gy = ((phy*invw + 1.0f) * (float)IMGH - 1.0f) * 0.5f;
    float depth = pvz;
    bool in_front = depth > 0.2f;
    float tz = in_front ? depth : 1.0f;
    const float lim = 1.3f * 0.5f;
    float txv = fminf(fmaxf(pvx/tz, -lim), lim) * tz;
    float tyv = fminf(fmaxf(pvy/tz, -lim), lim) * tz;
    const float fx = (float)IMGW / (2.0f*0.5f);
    const float fy = (float)IMGH / (2.0f*0.5f);
    float J00 = fx/tz, J02 = -fx*txv/(tz*tz);
    float J11 = fy/tz, J12 = -fy*tyv/(tz*tz);
    float T00 = J00*view[0] + J02*view[8];
    float T01 = J00*view[1] + J02*view[9];
    float T02 = J00*view[2] + J02*view[10];
    float T10 = J11*view[4] + J12*view[8];
    float T11 = J11*view[5] + J12*view[9];
    float T12 = J11*view[6] + J12*view[10];
    float u0 = c00*T00 + c01*T01 + c02*T02;
    float u1 = c01*T00 + c11*T01 + c12*T02;
    float u2 = c02*T00 + c12*T01 + c22*T02;
    float v0 = c00*T10 + c01*T11 + c02*T12;
    float v1 = c01*T10 + c11*T11 + c12*T12;
    float v2 = c02*T10 + c12*T11 + c22*T12;
    float a  = T00*u0 + T01*u1 + T02*u2 + 0.3f;
    float b  = T10*u0 + T11*u1 + T12*u2;
    float cc = T10*v0 + T11*v1 + T12*v2 + 0.3f;
    float det = a*cc - b*b;
    bool pos_det = det > 0.0f;
    float inv_det = pos_det ? 1.0f/det : 0.0f;
    float conA = cc*inv_det, conB = -b*inv_det, conC = a*inv_det;
    float mid = 0.5f*(a + cc);
    float lam = mid + sqrtf(fmaxf(mid*mid - det, 0.1f));
    bool visible = in_front && pos_det;
    float radius = visible ? ceilf(3.0f * sqrtf(lam)) : 0.0f;
    float op = opac[i];

    g_p0[i] = make_float4(gx, gy, radius, visible ? op : 0.0f);
    g_p1[i] = make_float4(conA, conB, conC, depth);
    g_dep[i] = depth;

    // TIGHT tile range (eps-widened superset of the exact bbox test).
    float c0f = fminf(fmaxf(ceilf ((gx - radius - 7.0f) * 0.125f - 1e-4f), 0.0f), 255.0f);
    float c1f = fminf(fmaxf(floorf((gx + radius) * 0.125f + 1e-4f), -1.0f), 255.0f);
    float r0f = fminf(fmaxf(ceilf ((gy - radius - 7.0f) * 0.125f - 1e-4f), 0.0f), 255.0f);
    float r1f = fminf(fmaxf(floorf((gy + radius) * 0.125f + 1e-4f), -1.0f), 255.0f);
    unsigned rng;
    if (visible && c1f >= c0f && r1f >= r0f)
        rng = (unsigned)c0f | ((unsigned)c1f << 8) | ((unsigned)r0f << 16) | ((unsigned)r1f << 24);
    else
        rng = 0x000000ffu;   // c0=255 > any c1 => never passes
    g_rng[i] = rng;

    out[3*NPIX + i]            = radius;
    out[3*NPIX + NG + i]       = (radius > 0.0f) ? 1.0f : 0.0f;
    out[3*NPIX + 2*NG + 2*i]   = gx;
    out[3*NPIX + 2*NG + 2*i+1] = gy;

#if __CUDA_ARCH__ >= 900
    cudaTriggerProgrammaticLaunchCompletion();
#endif
}

// One block per 8x8 tile, 512 threads = 64 pixels x 8 depth segments.
// Phase 1: cull via packed tile-range; store depth+gid per passing slot.
// Phase 2: rank-by-counting on (depth, slot); SCATTER full records from
//          L1-resident globals directly into sorted shared slots.
// Phase 3: segmented front-to-back blend, purely sequential shared reads.
__global__ void __launch_bounds__(NTHR) render_kernel(const float* __restrict__ bg,
                                                      float* __restrict__ out)
{
    extern __shared__ char dsm[];
    float4*  s_f0  = reinterpret_cast<float4*>(dsm);            // [NG] sorted
    float4*  s_c1  = reinterpret_cast<float4*>(dsm + 16384);    // [NG] sorted
    float2*  s_c2  = reinterpret_cast<float2*>(dsm + 32768);    // [NG] sorted
    float*   s_dep = reinterpret_cast<float*>(dsm + 40960);     // [NG] slot order
    unsigned short* s_gid = reinterpret_cast<unsigned short*>(dsm + 45056); // [NG]
    float4*  s_part = reinterpret_cast<float4*>(dsm + 47104);   // [NSEG*64]
    __shared__ int s_wcnt[32];
    __shared__ int s_woff[32];
    __shared__ int s_count;

    int lid  = threadIdx.x;
    int pixl = lid & 63;
    int seg  = lid >> 6;
    unsigned tx = blockIdx.x, ty = blockIdx.y;
    int warp = lid >> 5, lane = lid & 31;

#if __CUDA_ARCH__ >= 900
    cudaGridDependencySynchronize();
#endif

    // ---- Phase 1: range-based cull + compact (slot order == gid order) ----
    unsigned m[2];
    bool pass[2];
    #pragma unroll
    for (int c = 0; c < 2; c++) {
        unsigned rg = g_rng[c*NTHR + lid];
        pass[c] = ((rg & 0xffu) <= tx) && (((rg >> 8) & 0xffu) >= tx)
               && (((rg >> 16) & 0xffu) <= ty) && ((rg >> 24) >= ty);
        m[c] = __ballot_sync(0xffffffffu, pass[c]);
        if (lane == 0) s_wcnt[c*16 + warp] = __popc(m[c]);
    }
    __syncthreads();
    if (warp == 0) {
        int v = s_wcnt[lane];
        int s = v;
        #pragma unroll
        for (int d = 1; d < 32; d <<= 1) {
            int n = __shfl_up_sync(0xffffffffu, s, d);
            if (lane >= d) s += n;
        }
        s_woff[lane] = s - v;
        if (lane == 31) s_count = s;
    }
    __syncthreads();
    unsigned lmask = (1u << lane) - 1u;
    #pragma unroll
    for (int c = 0; c < 2; c++) {
        if (pass[c]) {
            int gid  = c*NTHR + lid;
            int slot = s_woff[c*16 + warp] + __popc(m[c] & lmask);
            s_dep[slot] = g_dep[gid];
            s_gid[slot] = (unsigned short)gid;
        }
    }
    __syncthreads();
    int count = s_count;

    // ---- Phase 2: rank + scatter into sorted order ----
    for (int s = lid; s < count; s += NTHR) {
        float k = s_dep[s];
        int r = 0;
        for (int j = 0; j < count; j++) {    // block-wide LDS broadcast
            float kj = s_dep[j];
            r += (kj < k || (kj == k && j < s)) ? 1 : 0;
        }
        int gid = s_gid[s];
        float4 f1 = g_p1[gid];               // L1-resident (48KB total)
        float4 f2 = g_p2[gid];
        s_f0[r] = g_p0[gid];
        s_c1[r] = make_float4(f1.x, f1.y, f1.z, f2.x);
        s_c2[r] = make_float2(f2.y, f2.z);
    }
    __syncthreads();

    // ---- Phase 3: segmented front-to-back blend (sequential shared) ----
    int L   = (count + NSEG - 1) / NSEG;
    int beg = seg * L;
    int end = min(beg + L, count);
    float fpx = (float)(tx*TS + (pixl & 7)), fpy = (float)(ty*TS + (pixl >> 3));
    float T = 1.0f, Cr = 0.0f, Cg = 0.0f, Cb = 0.0f;
    for (int i = beg; i < end; i++) {
        if ((i & 15) == 0 && !__ballot_sync(0xffffffffu, T > 6.1e-5f)) break;
        float4 f0 = s_f0[i];
        float ddx = f0.x - fpx, ddy = f0.y - fpy;
        if (fabsf(ddx) <= f0.z && fabsf(ddy) <= f0.z) {
            float4 c1 = s_c1[i];
            float power = -0.5f*(c1.x*ddx*ddx + c1.z*ddy*ddy) - c1.y*ddx*ddy;
            if (power <= 0.0f) {
                float alpha = fminf(0.99f, f0.w * __expf(power));
                if (alpha >= (1.0f/255.0f)) {
                    float2 c2 = s_c2[i];
                    float w = alpha * T;
                    Cr += w*c1.w; Cg += w*c2.x; Cb += w*c2.y;
                    T *= (1.0f - alpha);
                }
            }
        }
    }
    s_part[seg*64 + pixl] = make_float4(Cr, Cg, Cb, T);
    __syncthreads();

    if (lid < 64) {
        float cr = 0.0f, cg = 0.0f, cb = 0.0f, tt = 1.0f;
        #pragma unroll
        for (int s = 0; s < NSEG; s++) {
            float4 p = s_part[s*64 + lid];
            cr += tt*p.x; cg += tt*p.y; cb += tt*p.z;
            tt *= p.w;
        }
        int px = tx*TS + (lid & 7);
        int py = ty*TS + (lid >> 3);
        int pix = py*IMGW + px;
        out[pix]          = cr + tt*bg[0];
        out[NPIX + pix]   = cg + tt*bg[1];
        out[2*NPIX + pix] = cb + tt*bg[2];
    }
}

extern "C" void kernel_launch(void* const* d_in, const int* in_sizes, int n_in,
                              void* d_out, int out_size)
{
    const float* means3D    = (const float*)d_in[0];
    const float* scales     = (const float*)d_in[1];
    const float* rotations  = (const float*)d_in[2];
    const float* opacities  = (const float*)d_in[3];
    const float* shs        = (const float*)d_in[4];
    const float* viewmatrix = (const float*)d_in[5];
    const float* projmatrix = (const float*)d_in[6];
    const float* campos     = (const float*)d_in[7];
    const float* bg_color   = (const float*)d_in[8];
    float* out = (float*)d_out;

    cudaFuncSetAttribute(render_kernel,
                         cudaFuncAttributeMaxDynamicSharedMemorySize,
                         SMEM_BYTES);

    preprocess_kernel<<<32, 64>>>(means3D, scales, rotations, opacities, shs,
                                  viewmatrix, projmatrix, campos, out);

    cudaLaunchConfig_t cfg = {};
    cfg.gridDim = dim3(IMGW/TS, IMGH/TS, 1);
    cfg.blockDim = dim3(NTHR, 1, 1);
    cfg.dynamicSmemBytes = SMEM_BYTES;
    cfg.stream = 0;
    cudaLaunchAttribute attrs[1];
    attrs[0].id = cudaLaunchAttributeProgrammaticStreamSerialization;
    attrs[0].val.programmaticStreamSerializationAllowed = 1;
    cfg.attrs = attrs;
    cfg.numAttrs = 1;
    cudaLaunchKernelEx(&cfg, render_kernel, (const float*)bg_color, out);
}